// round 8
// baseline (speedup 1.0000x reference)
#include <cuda_runtime.h>
#include <cuda_bf16.h>
#include <cstdint>

// Problem constants
#define N_ROWS 8192
#define DIMK   1024
#define HALF_N 4096
#define INV_T  (1.0f / 0.07f)

#define TILE 128
#define KCH  64
#define KITERS 16
#define NBLK 64
#define NTRI 2080
#define NSPLIT 24                     // last tiles -> quarters
#define NFULL (NTRI - NSPLIT)         // 2056
#define NQUART (NSPLIT * 4)           // 96
#define NCTA 296                      // 2 persistent CTAs / SM

#define STAGE_BYTES (2 * TILE * 128)  // A 16KB + B 16KB (NI=8 view)
#define SMEM_DYN (3 * STAGE_BYTES)    // 96 KB

// Scratch (allocation-free rule: __device__ globals)
__device__ __nv_bfloat16 g_fb[N_ROWS * DIMK];
__device__ float         g_sumexp[N_ROWS];
__device__ float         g_pos[N_ROWS];

// ---------------------------------------------------------------------------
__device__ __forceinline__ uint32_t smem_u32(const void* p) {
    uint32_t a;
    asm("{ .reg .u64 t; cvta.to.shared.u64 t, %1; cvt.u32.u64 %0, t; }" : "=r"(a) : "l"(p));
    return a;
}
#define CP16(dst, src) \
    asm volatile("cp.async.cg.shared.global [%0], [%1], 16;" :: "r"(dst), "l"(src) : "memory")
#define CP_COMMIT() asm volatile("cp.async.commit_group;" ::: "memory")
#define CP_WAIT(n)  asm volatile("cp.async.wait_group %0;" :: "n"(n) : "memory")

#define LDSM_X4(r0, r1, r2, r3, addr)                                        \
    asm volatile("ldmatrix.sync.aligned.m8n8.x4.shared.b16 {%0,%1,%2,%3}, [%4];" \
        : "=r"(r0), "=r"(r1), "=r"(r2), "=r"(r3) : "r"(addr))

#define MMA_BF16(d, a, b)                                                    \
    asm volatile("mma.sync.aligned.m16n8k16.row.col.f32.bf16.bf16.f32 "      \
        "{%0,%1,%2,%3}, {%4,%5,%6,%7}, {%8,%9}, {%0,%1,%2,%3};"              \
        : "+f"((d)[0]), "+f"((d)[1]), "+f"((d)[2]), "+f"((d)[3])             \
        : "r"((a)[0]), "r"((a)[1]), "r"((a)[2]), "r"((a)[3]),                \
          "r"((b)[0]), "r"((b)[1]))

__device__ __forceinline__ uint32_t sw_off(int row, int kc) {
    return (uint32_t)(row * 128 + ((kc ^ (row & 7)) << 4));
}

// linear triangular index -> (bi, bj), bi <= bj
__device__ __forceinline__ void tile_coords(int t, int& bi, int& bj) {
    int b = (int)(64.5f - sqrtf(64.5f * 64.5f - 2.0f * (float)t));
    if (b < 0) b = 0;
    if (b >= NBLK) b = NBLK - 1;
    #pragma unroll 1
    while (b + 1 <= NBLK - 1 && (b + 1) * NBLK - ((b + 1) * b) / 2 <= t) b++;
    #pragma unroll 1
    while (b > 0 && b * NBLK - (b * (b - 1)) / 2 > t) b--;
    bi = b;
    bj = b + (t - (b * NBLK - (b * (b - 1)) / 2));
}

// ---------------------------------------------------------------------------
// Kernel A: normalize rows -> g_fb (bf16). Two rows per warp (double MLP).
// ---------------------------------------------------------------------------
__global__ void norm_kernel(const float* __restrict__ in, float* __restrict__ out) {
    const int warp = threadIdx.x >> 5;
    const int lane = threadIdx.x & 31;
    const int r0 = blockIdx.x * 16 + warp * 2;
    const int r1 = r0 + 1;

    const float4* s0 = reinterpret_cast<const float4*>(in + (size_t)r0 * DIMK);
    const float4* s1 = reinterpret_cast<const float4*>(in + (size_t)r1 * DIMK);
    float4 a[8], b[8];
    #pragma unroll
    for (int i = 0; i < 8; i++) { a[i] = s0[lane + i * 32]; b[i] = s1[lane + i * 32]; }

    float ssa = 0.f, ssb = 0.f;
    #pragma unroll
    for (int i = 0; i < 8; i++) {
        ssa += a[i].x * a[i].x + a[i].y * a[i].y + a[i].z * a[i].z + a[i].w * a[i].w;
        ssb += b[i].x * b[i].x + b[i].y * b[i].y + b[i].z * b[i].z + b[i].w * b[i].w;
    }
    #pragma unroll
    for (int m = 16; m; m >>= 1) {
        ssa += __shfl_xor_sync(0xffffffffu, ssa, m);
        ssb += __shfl_xor_sync(0xffffffffu, ssb, m);
    }
    const float ia = rsqrtf(ssa), ib = rsqrtf(ssb);

    uint2* d0 = reinterpret_cast<uint2*>(g_fb + (size_t)r0 * DIMK);
    uint2* d1 = reinterpret_cast<uint2*>(g_fb + (size_t)r1 * DIMK);
    #pragma unroll
    for (int i = 0; i < 8; i++) {
        __nv_bfloat162 p0 = __floats2bfloat162_rn(a[i].x * ia, a[i].y * ia);
        __nv_bfloat162 p1 = __floats2bfloat162_rn(a[i].z * ia, a[i].w * ia);
        d0[lane + i * 32] = make_uint2(*reinterpret_cast<uint32_t*>(&p0),
                                       *reinterpret_cast<uint32_t*>(&p1));
        __nv_bfloat162 q0 = __floats2bfloat162_rn(b[i].x * ib, b[i].y * ib);
        __nv_bfloat162 q1 = __floats2bfloat162_rn(b[i].z * ib, b[i].w * ib);
        d1[lane + i * 32] = make_uint2(*reinterpret_cast<uint32_t*>(&q0),
                                       *reinterpret_cast<uint32_t*>(&q1));
    }
    if (lane == 0) { g_sumexp[r0] = 0.f; g_sumexp[r1] = 0.f; }
    if (r0 == 0 && lane == 0) out[0] = 0.f;   // d_out poisoned
}

// ---------------------------------------------------------------------------
// GEMM building blocks, templated on NI (per-warp n-blocks of 8 cols).
// NI=8: 128x128 tile (warp 32x64). NI=2: 128x32 quarter (warp 32x16).
// ---------------------------------------------------------------------------
template<int NI>
__device__ __forceinline__ void load_unit_tile(uint32_t sA, uint32_t sB,
                                               int rowBase, int colBase, int k0, int tid) {
    #pragma unroll
    for (int i = 0; i < 4; i++) {
        int c = tid + i * 256;
        int row = c >> 3, kc = c & 7;
        CP16(sA + sw_off(row, kc),
             g_fb + (size_t)(rowBase + row) * DIMK + k0 + kc * 8);
    }
    #pragma unroll
    for (int i = 0; i < NI / 2; i++) {
        int c = tid + i * 256;
        int row = c >> 3, kc = c & 7;
        CP16(sB + sw_off(row, kc),
             g_fb + (size_t)(colBase + row) * DIMK + k0 + kc * 8);
    }
    CP_COMMIT();
}

template<int NI>
__device__ __forceinline__ void compute_ktile(float (&acc)[2][NI][4],
                                              uint32_t a_base, uint32_t b_base,
                                              int lane, int warp_m, int warp_n) {
    #pragma unroll
    for (int ks = 0; ks < 4; ks++) {
        uint32_t a[2][4];
        #pragma unroll
        for (int mi = 0; mi < 2; mi++) {
            int row = warp_m * 32 + mi * 16 + (lane & 15);
            int kc = ks * 2 + (lane >> 4);
            LDSM_X4(a[mi][0], a[mi][1], a[mi][2], a[mi][3], a_base + sw_off(row, kc));
        }
        uint32_t b[NI][2];
        #pragma unroll
        for (int nq = 0; nq < NI / 2; nq++) {
            int nrow = warp_n * (NI * 8) + nq * 16 + (((lane >> 4) << 3) | (lane & 7));
            int kc = ks * 2 + ((lane >> 3) & 1);
            uint32_t t0, t1, t2, t3;
            LDSM_X4(t0, t1, t2, t3, b_base + sw_off(nrow, kc));
            b[nq * 2][0] = t0;     b[nq * 2][1] = t1;
            b[nq * 2 + 1][0] = t2; b[nq * 2 + 1][1] = t3;
        }
        #pragma unroll
        for (int mi = 0; mi < 2; mi++)
            #pragma unroll
            for (int ni = 0; ni < NI; ni++)
                MMA_BF16(acc[mi][ni], a[mi], b[ni]);
    }
}

// Epilogue with direct global atomics (no smem, no barriers).
template<int NI>
__device__ __forceinline__ void epilogue(float (&acc)[2][NI][4],
                                         int rowBase, int colBase, bool diag, bool posTile,
                                         int lane, int warp_m, int warp_n) {
    const int g = lane >> 2;
    const int q4 = lane & 3;

    float csE[NI], csO[NI];
    #pragma unroll
    for (int ni = 0; ni < NI; ni++) { csE[ni] = 0.f; csO[ni] = 0.f; }

    #pragma unroll
    for (int mi = 0; mi < 2; mi++) {
        float rs0 = 0.f, rs1 = 0.f;
        const int ra = rowBase + warp_m * 32 + mi * 16 + g;
        const int rb = ra + 8;
        #pragma unroll
        for (int ni = 0; ni < NI; ni++) {
            const int cb = colBase + warp_n * (NI * 8) + ni * 8 + q4 * 2;
            const float v0 = acc[mi][ni][0], v1 = acc[mi][ni][1];
            const float v2 = acc[mi][ni][2], v3 = acc[mi][ni][3];

            if (posTile) {
                if (cb     == ra + HALF_N) { g_pos[ra] = v0; g_pos[cb]     = v0; }
                if (cb + 1 == ra + HALF_N) { g_pos[ra] = v1; g_pos[cb + 1] = v1; }
                if (cb     == rb + HALF_N) { g_pos[rb] = v2; g_pos[cb]     = v2; }
                if (cb + 1 == rb + HALF_N) { g_pos[rb] = v3; g_pos[cb + 1] = v3; }
            }

            float e0 = __expf(v0 * INV_T);
            float e1 = __expf(v1 * INV_T);
            float e2 = __expf(v2 * INV_T);
            float e3 = __expf(v3 * INV_T);
            if (ra == cb)     e0 = 0.f;
            if (ra == cb + 1) e1 = 0.f;
            if (rb == cb)     e2 = 0.f;
            if (rb == cb + 1) e3 = 0.f;
            rs0 += e0 + e1;
            rs1 += e2 + e3;
            csE[ni] += e0 + e2;
            csO[ni] += e1 + e3;
        }
        rs0 += __shfl_xor_sync(0xffffffffu, rs0, 1);
        rs0 += __shfl_xor_sync(0xffffffffu, rs0, 2);
        rs1 += __shfl_xor_sync(0xffffffffu, rs1, 1);
        rs1 += __shfl_xor_sync(0xffffffffu, rs1, 2);
        if (q4 == 0) {
            atomicAdd(&g_sumexp[ra], rs0);
            atomicAdd(&g_sumexp[rb], rs1);
        }
    }

    #pragma unroll
    for (int ni = 0; ni < NI; ni++) {
        float vE = csE[ni], vO = csO[ni];
        #pragma unroll
        for (int m = 4; m <= 16; m <<= 1) {
            vE += __shfl_xor_sync(0xffffffffu, vE, m);
            vO += __shfl_xor_sync(0xffffffffu, vO, m);
        }
        if (lane < 4 && !diag) {
            const int c = colBase + warp_n * (NI * 8) + ni * 8 + q4 * 2;
            atomicAdd(&g_sumexp[c], vE);
            atomicAdd(&g_sumexp[c + 1], vO);
        }
    }
}

// ---------------------------------------------------------------------------
// Kernel B: persistent. Phase 1: continuous pipeline over full tiles
// (static stride schedule). Phase 2: quarter tiles (tail smoothing).
// ---------------------------------------------------------------------------
__global__ __launch_bounds__(256, 2) void simexp_kernel() {
    extern __shared__ __align__(16) char dsmem[];
    const int tid = threadIdx.x;
    const int lane = tid & 31;
    const int wid = tid >> 5;
    const int warp_m = wid & 3;
    const int warp_n = wid >> 2;
    const int cta = blockIdx.x;

    uint32_t sbase = smem_u32(dsmem);
    uint32_t sAu[3], sBu[3];
    #pragma unroll
    for (int s = 0; s < 3; s++) {
        sAu[s] = sbase + s * STAGE_BYTES;
        sBu[s] = sAu[s] + TILE * 128;
    }

    // ---- Phase 1: full tiles t = cta + 296*u ----
    const int nf = (cta < 280) ? 7 : 6;      // covers t in [0, 2056) exactly
    const int J = nf * KITERS;

    float acc[2][8][4];
    int lu = -1, lrow = 0, lcol = 0;         // load-side tile cache
    int cu = -1, crow = 0, ccol = 0;         // compute-side tile cache
    bool cdiag = false, cpos = false;

    auto issue = [&](int gidx) {
        if (gidx < J) {
            int u = gidx >> 4;
            if (u != lu) {
                lu = u;
                int bi, bj;
                tile_coords(cta + NCTA * u, bi, bj);
                lrow = bi * 128; lcol = bj * 128;
            }
            load_unit_tile<8>(sAu[gidx % 3], sBu[gidx % 3], lrow, lcol,
                              (gidx & 15) * KCH, tid);
        } else {
            CP_COMMIT();
        }
    };

    issue(0);
    issue(1);

    #pragma unroll 1
    for (int j = 0; j < J; j++) {
        CP_WAIT(1);
        __syncthreads();
        issue(j + 2);

        if ((j >> 4) != cu) {
            cu = j >> 4;
            int bi, bj;
            tile_coords(cta + NCTA * cu, bi, bj);
            crow = bi * 128; ccol = bj * 128;
            cdiag = (bi == bj);
            cpos = (bj - bi == 32);
            #pragma unroll
            for (int mi = 0; mi < 2; mi++)
                #pragma unroll
                for (int ni = 0; ni < 8; ni++)
                    #pragma unroll
                    for (int k = 0; k < 4; k++) acc[mi][ni][k] = 0.f;
        }

        compute_ktile<8>(acc, sAu[j % 3], sBu[j % 3], lane, warp_m, warp_n);

        if ((j & 15) == 15)
            epilogue<8>(acc, crow, ccol, cdiag, cpos, lane, warp_m, warp_n);
    }
    CP_WAIT(0);
    __syncthreads();

    // ---- Phase 2: quarter tiles (128x32) from the last NSPLIT tiles ----
    int qstart = 0, qcount = 0;
    if (cta >= 280)     { qstart = (cta - 280) * 4; qcount = 4; }
    else if (cta < 32)  { qstart = 64 + cta;        qcount = 1; }

    #pragma unroll 1
    for (int qi = 0; qi < qcount; qi++) {
        const int q = qstart + qi;
        int bi, bj;
        tile_coords(NFULL + (q >> 2), bi, bj);
        const int rB = bi * 128;
        const int cB = bj * 128 + (q & 3) * 32;
        const bool dg = (bi == bj);

        float qacc[2][2][4];
        #pragma unroll
        for (int mi = 0; mi < 2; mi++)
            #pragma unroll
            for (int ni = 0; ni < 2; ni++)
                #pragma unroll
                for (int k = 0; k < 4; k++) qacc[mi][ni][k] = 0.f;

        load_unit_tile<2>(sAu[0], sBu[0], rB, cB, 0, tid);
        load_unit_tile<2>(sAu[1], sBu[1], rB, cB, KCH, tid);

        #pragma unroll 1
        for (int j = 0; j < KITERS; j++) {
            CP_WAIT(1);
            __syncthreads();
            if (j + 2 < KITERS)
                load_unit_tile<2>(sAu[(j + 2) % 3], sBu[(j + 2) % 3], rB, cB,
                                  (j + 2) * KCH, tid);
            else
                CP_COMMIT();
            compute_ktile<2>(qacc, sAu[j % 3], sBu[j % 3], lane, warp_m, warp_n);
        }
        epilogue<2>(qacc, rB, cB, dg, false, lane, warp_m, warp_n);
        CP_WAIT(0);
        __syncthreads();
    }
}

// ---------------------------------------------------------------------------
// Kernel C: finalize. loss_i = log(sumexp_i) - pos_i / T ; mean via atomics.
// ---------------------------------------------------------------------------
__global__ void finalize_kernel(float* __restrict__ out) {
    int i = blockIdx.x * 256 + threadIdx.x;
    float loss = logf(g_sumexp[i]) - g_pos[i] * INV_T;

    #pragma unroll
    for (int m = 16; m; m >>= 1) loss += __shfl_xor_sync(0xffffffffu, loss, m);
    __shared__ float ws[8];
    if ((threadIdx.x & 31) == 0) ws[threadIdx.x >> 5] = loss;
    __syncthreads();
    if (threadIdx.x == 0) {
        float s = 0.f;
        #pragma unroll
        for (int k = 0; k < 8; k++) s += ws[k];
        atomicAdd(out, s * (1.0f / N_ROWS));
    }
}

// ---------------------------------------------------------------------------
extern "C" void kernel_launch(void* const* d_in, const int* in_sizes, int n_in,
                              void* d_out, int out_size) {
    const float* features = (const float*)d_in[0];
    float* out = (float*)d_out;

    static bool configured = false;
    if (!configured) {
        cudaFuncSetAttribute(simexp_kernel,
                             cudaFuncAttributeMaxDynamicSharedMemorySize, SMEM_DYN);
        configured = true;
    }

    norm_kernel<<<N_ROWS / 16, 256>>>(features, out);
    simexp_kernel<<<NCTA, 256, SMEM_DYN>>>();
    finalize_kernel<<<N_ROWS / 256, 256>>>(out);
}